// round 1
// baseline (speedup 1.0000x reference)
#include <cuda_runtime.h>
#include <math.h>

#define BATCH 4
#define CH    256
#define CKDIM 64
#define NPIX  4096   // 64*64
#define EPS   1e-5f

// ---------------- device scratch (static, allocation-free) ----------------
__device__ __align__(16) float g_scale[CH];
__device__ __align__(16) float g_shift[CH];
__device__ __align__(16) float g_Q[BATCH * NPIX * CKDIM];            // [b][n][64]
__device__ __align__(16) float g_K[BATCH * NPIX * CKDIM];            // [b][n][64]
__device__ __align__(16) float g_V[(size_t)BATCH * NPIX * CH];       // [b][n][256]
__device__ __align__(16) float g_S[(size_t)BATCH * NPIX * NPIX];     // [b][i][j], 256 MB

// ---------------- kernel 0: fold BN into per-channel affine ----------------
__global__ void prep_kernel(const float* __restrict__ gamma,
                            const float* __restrict__ beta,
                            const float* __restrict__ mean,
                            const float* __restrict__ var) {
    int c = threadIdx.x;
    if (c < CH) {
        float s = gamma[c] * rsqrtf(var[c] + EPS);
        g_scale[c] = s;
        g_shift[c] = beta[c] - mean[c] * s;
    }
}

// ---------------- kernel 1: projection GEMM ----------------
// out[b][n][k] = sum_c W[k,c] * (x[b,c,n]*scale[c]+shift[c]) + bias[k]
// grid: (NPIX/64, KOUT/64, BATCH), 256 threads, 64x64 tile, 4x4 micro (stride-16)
template<int KOUT, bool USE_BN>
__global__ void proj_kernel(const float* __restrict__ x,
                            const float* __restrict__ W,
                            const float* __restrict__ bias,
                            float* __restrict__ out) {
    __shared__ float As[16][65];   // As[cc][nn]
    __shared__ float Bs[16][65];   // Bs[cc][kk]
    const int b  = blockIdx.z;
    const int n0 = blockIdx.x * 64;
    const int k0 = blockIdx.y * 64;
    const float* xb = x + (size_t)b * CH * NPIX;
    const int tid = threadIdx.x;
    const int tk = tid & 15;     // fast: k
    const int tn = tid >> 4;     // slow: n

    float acc[4][4] = {};

    for (int c0 = 0; c0 < CH; c0 += 16) {
        // load A tile (x, BN applied): 16c x 64n
        {
            int nn = tid & 63;
            int cb = tid >> 6;            // 0..3
            #pragma unroll
            for (int r = 0; r < 4; ++r) {
                int cc = cb + r * 4;
                float v = xb[(size_t)(c0 + cc) * NPIX + n0 + nn];
                if (USE_BN) v = v * g_scale[c0 + cc] + g_shift[c0 + cc];
                As[cc][nn] = v;
            }
        }
        // load B tile (weights): Bs[cc][kk] = W[(k0+kk)*CH + c0+cc]
        {
            int cc = tid & 15;
            int kb = tid >> 4;            // 0..15
            #pragma unroll
            for (int r = 0; r < 4; ++r) {
                int kk = kb + r * 16;
                Bs[cc][kk] = W[(size_t)(k0 + kk) * CH + c0 + cc];
            }
        }
        __syncthreads();
        #pragma unroll
        for (int cc = 0; cc < 16; ++cc) {
            float a[4], bv[4];
            #pragma unroll
            for (int i = 0; i < 4; ++i) a[i]  = As[cc][tn + i * 16];
            #pragma unroll
            for (int j = 0; j < 4; ++j) bv[j] = Bs[cc][tk + j * 16];
            #pragma unroll
            for (int i = 0; i < 4; ++i)
                #pragma unroll
                for (int j = 0; j < 4; ++j) acc[i][j] += a[i] * bv[j];
        }
        __syncthreads();
    }

    float* ob = out + (size_t)b * NPIX * KOUT;
    #pragma unroll
    for (int i = 0; i < 4; ++i) {
        int n = n0 + tn + i * 16;
        #pragma unroll
        for (int j = 0; j < 4; ++j) {
            int k = k0 + tk + j * 16;
            ob[(size_t)n * KOUT + k] = acc[i][j] + bias[k];
        }
    }
}

// ---------------- kernel 2: scores = Q @ K^T ----------------
// S[b][i][j] = dot(Q[b][i][:], K[b][j][:]); grid (N/64 [j], N/64 [i], B), 256 thr
__global__ void qk_kernel(const float* __restrict__ Q,
                          const float* __restrict__ K,
                          float* __restrict__ S) {
    __shared__ float Qs[64][65];   // [kdim][i]
    __shared__ float Ks[64][65];   // [kdim][j]
    const int b  = blockIdx.z;
    const int j0 = blockIdx.x * 64;
    const int i0 = blockIdx.y * 64;
    const float* Qb = Q + ((size_t)b * NPIX + i0) * CKDIM;
    const float* Kb = K + ((size_t)b * NPIX + j0) * CKDIM;
    const int tid = threadIdx.x;

    // cooperative transposed load (float4 in, scalar smem out)
    {
        int c4 = (tid & 15) * 4;
        int rr = tid >> 4;
        #pragma unroll
        for (int p = 0; p < 4; ++p) {
            int row = rr + p * 16;
            float4 q4 = *(const float4*)(Qb + (size_t)row * CKDIM + c4);
            Qs[c4 + 0][row] = q4.x; Qs[c4 + 1][row] = q4.y;
            Qs[c4 + 2][row] = q4.z; Qs[c4 + 3][row] = q4.w;
            float4 k4 = *(const float4*)(Kb + (size_t)row * CKDIM + c4);
            Ks[c4 + 0][row] = k4.x; Ks[c4 + 1][row] = k4.y;
            Ks[c4 + 2][row] = k4.z; Ks[c4 + 3][row] = k4.w;
        }
    }
    __syncthreads();

    const int tj = tid & 15;
    const int ti = tid >> 4;
    float acc[4][4] = {};
    #pragma unroll
    for (int kk = 0; kk < 64; ++kk) {
        float a[4], bv[4];
        #pragma unroll
        for (int i = 0; i < 4; ++i) a[i]  = Qs[kk][ti + i * 16];
        #pragma unroll
        for (int j = 0; j < 4; ++j) bv[j] = Ks[kk][tj + j * 16];
        #pragma unroll
        for (int i = 0; i < 4; ++i)
            #pragma unroll
            for (int j = 0; j < 4; ++j) acc[i][j] += a[i] * bv[j];
    }

    #pragma unroll
    for (int i = 0; i < 4; ++i) {
        size_t roff = ((size_t)b * NPIX + i0 + ti + i * 16) * NPIX + j0;
        #pragma unroll
        for (int j = 0; j < 4; ++j)
            S[roff + tj + j * 16] = acc[i][j];
    }
}

// ---------------- kernel 3: row softmax -> att = 1/(1+exp(p)) in-place ------
// grid (NPIX, BATCH), 256 threads, 16 elems/thread in registers
__global__ void att_kernel(float* __restrict__ S) {
    float* r = S + ((size_t)blockIdx.y * NPIX + blockIdx.x) * (size_t)NPIX;
    const int t = threadIdx.x;
    const int lane = t & 31, wid = t >> 5;
    __shared__ float smax[8];
    __shared__ float ssum[8];

    float v[16];
    float mx = -1e30f;
    #pragma unroll
    for (int q = 0; q < 16; ++q) { v[q] = r[t + q * 256]; mx = fmaxf(mx, v[q]); }
    #pragma unroll
    for (int o = 16; o; o >>= 1) mx = fmaxf(mx, __shfl_xor_sync(0xffffffffu, mx, o));
    if (lane == 0) smax[wid] = mx;
    __syncthreads();
    mx = smax[0];
    #pragma unroll
    for (int w = 1; w < 8; ++w) mx = fmaxf(mx, smax[w]);

    float s = 0.f;
    #pragma unroll
    for (int q = 0; q < 16; ++q) { v[q] = expf(v[q] - mx); s += v[q]; }
    #pragma unroll
    for (int o = 16; o; o >>= 1) s += __shfl_xor_sync(0xffffffffu, s, o);
    if (lane == 0) ssum[wid] = s;
    __syncthreads();
    float Z = 0.f;
    #pragma unroll
    for (int w = 0; w < 8; ++w) Z += ssum[w];
    float inv = 1.0f / Z;

    #pragma unroll
    for (int q = 0; q < 16; ++q) {
        float p = v[q] * inv;                 // softmax value
        r[t + q * 256] = 1.0f / (1.0f + expf(p));  // 1 - sigmoid(p)
    }
}

// ---------------- kernel 4: out[b,c,m] = alpha * sum_n att[m,n]*V[n,c] + x ---
// grid (NPIX/128 [m], CH/128 [c], BATCH), 256 threads, 128x128x32 tiles, 8x8 micro
__global__ void pv_kernel(const float* __restrict__ V,
                          const float* __restrict__ S,
                          const float* __restrict__ xres,
                          const float* __restrict__ alpha,
                          float* __restrict__ out) {
    __shared__ float As[32][133];  // att transposed: As[kk][mm]
    __shared__ float Bs[32][128];  // V: Bs[kk][cc]
    const int b  = blockIdx.z;
    const int m0 = blockIdx.x * 128;
    const int c0 = blockIdx.y * 128;
    const float* Sb = S + ((size_t)b * NPIX + m0) * (size_t)NPIX;
    const float* Vb = V + (size_t)b * NPIX * CH;
    const int tid = threadIdx.x;
    const int tm = tid & 15;   // fast: m  (coalesced epilogue)
    const int tc = tid >> 4;   // slow: c

    float acc[8][8] = {};

    for (int n0 = 0; n0 < NPIX; n0 += 32) {
        // att tile: 128 m-rows x 32 n, transposed into smem
        {
            int kk4 = (tid & 7) * 4;
            int mm  = tid >> 3;
            #pragma unroll
            for (int p = 0; p < 4; ++p) {
                int row = mm + p * 32;
                float4 a4 = *(const float4*)(Sb + (size_t)row * NPIX + n0 + kk4);
                As[kk4 + 0][row] = a4.x; As[kk4 + 1][row] = a4.y;
                As[kk4 + 2][row] = a4.z; As[kk4 + 3][row] = a4.w;
            }
        }
        // V tile: 32 n-rows x 128 c
        {
            int cc4 = (tid & 31) * 4;
            int kk  = tid >> 5;
            #pragma unroll
            for (int p = 0; p < 4; ++p) {
                int row = kk + p * 8;
                *(float4*)&Bs[row][cc4] =
                    *(const float4*)(Vb + (size_t)(n0 + row) * CH + c0 + cc4);
            }
        }
        __syncthreads();
        #pragma unroll
        for (int kk = 0; kk < 32; ++kk) {
            float a[8], bv[8];
            #pragma unroll
            for (int i = 0; i < 8; ++i) a[i]  = As[kk][tm + i * 16];
            #pragma unroll
            for (int j = 0; j < 8; ++j) bv[j] = Bs[kk][tc + j * 16];
            #pragma unroll
            for (int i = 0; i < 8; ++i)
                #pragma unroll
                for (int j = 0; j < 8; ++j) acc[i][j] += a[i] * bv[j];
        }
        __syncthreads();
    }

    const float al = alpha[0];
    #pragma unroll
    for (int j = 0; j < 8; ++j) {
        int c = c0 + tc + j * 16;
        const float* xr = xres + ((size_t)b * CH + c) * NPIX;
        float* orow     = out  + ((size_t)b * CH + c) * NPIX;
        #pragma unroll
        for (int i = 0; i < 8; ++i) {
            int m = m0 + tm + i * 16;
            orow[m] = al * acc[i][j] + xr[m];
        }
    }
}

// ---------------- launch ----------------
extern "C" void kernel_launch(void* const* d_in, const int* in_sizes, int n_in,
                              void* d_out, int out_size) {
    const float* x1    = (const float*)d_in[0];
    const float* x2    = (const float*)d_in[1];
    const float* x     = (const float*)d_in[2];
    const float* gamma = (const float*)d_in[3];
    const float* beta  = (const float*)d_in[4];
    const float* mean  = (const float*)d_in[5];
    const float* var   = (const float*)d_in[6];
    const float* Wb    = (const float*)d_in[7];
    const float* bb    = (const float*)d_in[8];
    const float* Wc    = (const float*)d_in[9];
    const float* bc    = (const float*)d_in[10];
    const float* Wd    = (const float*)d_in[11];
    const float* bd    = (const float*)d_in[12];
    const float* alpha = (const float*)d_in[13];
    float* out = (float*)d_out;

    float *Qp, *Kp, *Vp, *Sp;
    cudaGetSymbolAddress((void**)&Qp, g_Q);
    cudaGetSymbolAddress((void**)&Kp, g_K);
    cudaGetSymbolAddress((void**)&Vp, g_V);
    cudaGetSymbolAddress((void**)&Sp, g_S);

    prep_kernel<<<1, 256>>>(gamma, beta, mean, var);

    proj_kernel<CKDIM, true ><<<dim3(NPIX / 64, 1, BATCH), 256>>>(x1, Wb, bb, Qp);
    proj_kernel<CKDIM, true ><<<dim3(NPIX / 64, 1, BATCH), 256>>>(x2, Wc, bc, Kp);
    proj_kernel<CH,    false><<<dim3(NPIX / 64, CH / 64, BATCH), 256>>>(x, Wd, bd, Vp);

    qk_kernel<<<dim3(NPIX / 64, NPIX / 64, BATCH), 256>>>(Qp, Kp, Sp);

    att_kernel<<<dim3(NPIX, BATCH), 256>>>(Sp);

    pv_kernel<<<dim3(NPIX / 128, CH / 128, BATCH), 256>>>(Vp, Sp, x, alpha, out);
}

// round 3
// speedup vs baseline: 2.3376x; 2.3376x over previous
#include <cuda_runtime.h>
#include <cuda_bf16.h>
#include <mma.h>
#include <math.h>
#include <stdint.h>

using namespace nvcuda;

#define BATCH 4
#define CH    256
#define CKDIM 64
#define NPIX  4096
#define EPS   1e-5f
#define LDT   72            // smem tile leading dim (bf16 elements), 144B rows

#define DINL __device__ __forceinline__

// ---------------- device scratch (static, allocation-free) ----------------
__device__ __align__(16) float g_scale[CH];
__device__ __align__(16) float g_shift[CH];
__device__ __align__(16) __nv_bfloat16 g_Qb[BATCH * NPIX * CKDIM];        // [b][i][64]
__device__ __align__(16) __nv_bfloat16 g_Kb[BATCH * NPIX * CKDIM];        // [b][j][64]
__device__ __align__(16) __nv_bfloat16 g_VH[(size_t)BATCH * CH * NPIX];   // [b][c][n]
__device__ __align__(16) __nv_bfloat16 g_VL[(size_t)BATCH * CH * NPIX];
__device__ __align__(16) float         g_S [(size_t)BATCH * NPIX * NPIX]; // fp32 scores
__device__ __align__(16) __nv_bfloat16 g_AH[(size_t)BATCH * NPIX * NPIX]; // att hi
__device__ __align__(16) __nv_bfloat16 g_AL[(size_t)BATCH * NPIX * NPIX]; // att lo

// ---------------- portable async-copy helpers (sm_80+ PTX, no 'a' features) --
DINL uint32_t smem_u32(const void* p) {
    uint32_t a;
    asm("{ .reg .u64 t; cvta.to.shared.u64 t, %1; cvt.u32.u64 %0, t; }"
        : "=r"(a) : "l"(p));
    return a;
}
DINL void cpa16(uint32_t dst, const void* src) {
    asm volatile("cp.async.cg.shared.global [%0], [%1], 16;"
                 :: "r"(dst), "l"(src) : "memory");
}
DINL void cpa_commit() { asm volatile("cp.async.commit_group;" ::: "memory"); }
template<int N> DINL void cpa_wait() {
    asm volatile("cp.async.wait_group %0;" :: "n"(N) : "memory");
}

// ---------------- kernel 0: fold BN ----------------
__global__ void prep_kernel(const float* __restrict__ gamma,
                            const float* __restrict__ beta,
                            const float* __restrict__ mean,
                            const float* __restrict__ var) {
    int c = threadIdx.x;
    if (c < CH) {
        float s = gamma[c] * rsqrtf(var[c] + EPS);
        g_scale[c] = s;
        g_shift[c] = beta[c] - mean[c] * s;
    }
}

// ---------------- kernel 1a: Q/K projection (BN folded), bf16 out [b][n][64] --
__global__ void projqk_kernel(const float* __restrict__ x,
                              const float* __restrict__ W,
                              const float* __restrict__ bias,
                              __nv_bfloat16* __restrict__ out) {
    __shared__ float As[16][65];
    __shared__ float Bs[16][65];
    const int b  = blockIdx.z;
    const int n0 = blockIdx.x * 64;
    const float* xb = x + (size_t)b * CH * NPIX;
    const int tid = threadIdx.x;
    const int tk = tid & 15;
    const int tn = tid >> 4;

    float acc[4][4] = {};
    for (int c0 = 0; c0 < CH; c0 += 16) {
        {
            int nn = tid & 63, cb = tid >> 6;
            #pragma unroll
            for (int r = 0; r < 4; ++r) {
                int cc = cb + r * 4;
                float v = xb[(size_t)(c0 + cc) * NPIX + n0 + nn];
                As[cc][nn] = v * g_scale[c0 + cc] + g_shift[c0 + cc];
            }
        }
        {
            int cc = tid & 15, kb = tid >> 4;
            #pragma unroll
            for (int r = 0; r < 4; ++r) {
                int kk = kb + r * 16;
                Bs[cc][kk] = W[(size_t)kk * CH + c0 + cc];
            }
        }
        __syncthreads();
        #pragma unroll
        for (int cc = 0; cc < 16; ++cc) {
            float a[4], bv[4];
            #pragma unroll
            for (int i = 0; i < 4; ++i) a[i]  = As[cc][tn + i * 16];
            #pragma unroll
            for (int j = 0; j < 4; ++j) bv[j] = Bs[cc][tk + j * 16];
            #pragma unroll
            for (int i = 0; i < 4; ++i)
                #pragma unroll
                for (int j = 0; j < 4; ++j) acc[i][j] += a[i] * bv[j];
        }
        __syncthreads();
    }
    __nv_bfloat16* ob = out + (size_t)b * NPIX * CKDIM;
    #pragma unroll
    for (int i = 0; i < 4; ++i) {
        int n = n0 + tn + i * 16;
        #pragma unroll
        for (int j = 0; j < 4; ++j) {
            int k = tk + j * 16;
            ob[(size_t)n * CKDIM + k] = __float2bfloat16(acc[i][j] + bias[k]);
        }
    }
}

// ---------------- kernel 1b: V projection, split hi/lo bf16, [b][d][n] ------
__global__ void projv_kernel(const float* __restrict__ x,
                             const float* __restrict__ W,
                             const float* __restrict__ bias,
                             __nv_bfloat16* __restrict__ vh,
                             __nv_bfloat16* __restrict__ vl) {
    __shared__ float As[16][65];
    __shared__ float Bs[16][65];
    const int b  = blockIdx.z;
    const int n0 = blockIdx.x * 64;
    const int d0 = blockIdx.y * 64;
    const float* xb = x + (size_t)b * CH * NPIX;
    const int tid = threadIdx.x;
    const int tn = tid & 15;
    const int td = tid >> 4;

    float acc[4][4] = {};
    for (int c0 = 0; c0 < CH; c0 += 16) {
        {
            int nn = tid & 63, cb = tid >> 6;
            #pragma unroll
            for (int r = 0; r < 4; ++r) {
                int cc = cb + r * 4;
                As[cc][nn] = xb[(size_t)(c0 + cc) * NPIX + n0 + nn];
            }
        }
        {
            int cc = tid & 15, db = tid >> 4;
            #pragma unroll
            for (int r = 0; r < 4; ++r) {
                int dd = db + r * 16;
                Bs[cc][dd] = W[(size_t)(d0 + dd) * CH + c0 + cc];
            }
        }
        __syncthreads();
        #pragma unroll
        for (int cc = 0; cc < 16; ++cc) {
            float a[4], w[4];
            #pragma unroll
            for (int j = 0; j < 4; ++j) a[j] = As[cc][tn + j * 16];
            #pragma unroll
            for (int i = 0; i < 4; ++i) w[i] = Bs[cc][td + i * 16];
            #pragma unroll
            for (int i = 0; i < 4; ++i)
                #pragma unroll
                for (int j = 0; j < 4; ++j) acc[i][j] += w[i] * a[j];
        }
        __syncthreads();
    }
    #pragma unroll
    for (int i = 0; i < 4; ++i) {
        int d = d0 + td + i * 16;
        float bd_ = bias[d];
        #pragma unroll
        for (int j = 0; j < 4; ++j) {
            int n = n0 + tn + j * 16;
            float v = acc[i][j] + bd_;
            __nv_bfloat16 h = __float2bfloat16(v);
            size_t o = ((size_t)b * CH + d) * NPIX + n;
            vh[o] = h;
            vl[o] = __float2bfloat16(v - __bfloat162float(h));
        }
    }
}

// ---------------- kernel 2: scores = Q @ K^T via wmma bf16 ------------------
// CTA 128i x 128j, 8 warps (wm 0..3 x wc 0..1), warp tile 32i x 64j
__global__ __launch_bounds__(256) void qk_wmma_kernel(const __nv_bfloat16* __restrict__ Qb,
                                                      const __nv_bfloat16* __restrict__ Kb,
                                                      float* __restrict__ S) {
    __shared__ __align__(32) __nv_bfloat16 Qs[128 * LDT];
    __shared__ __align__(32) __nv_bfloat16 Ks[128 * LDT];
    const int tid = threadIdx.x, w = tid >> 5;
    const int b  = blockIdx.z;
    const int i0 = blockIdx.y * 128;
    const int j0 = blockIdx.x * 128;

    const uint4* gQ = (const uint4*)(Qb + ((size_t)b * NPIX + i0) * CKDIM);
    const uint4* gK = (const uint4*)(Kb + ((size_t)b * NPIX + j0) * CKDIM);
    #pragma unroll
    for (int p = 0; p < 4; ++p) {
        int idx = tid + p * 256;
        int row = idx >> 3, c8 = idx & 7;
        *(uint4*)&Qs[row * LDT + c8 * 8] = gQ[idx];
        *(uint4*)&Ks[row * LDT + c8 * 8] = gK[idx];
    }
    __syncthreads();

    const int wm = w >> 1, wc = w & 1;
    wmma::fragment<wmma::accumulator, 16, 16, 16, float> acc[2][4];
    #pragma unroll
    for (int mi = 0; mi < 2; ++mi)
        #pragma unroll
        for (int nj = 0; nj < 4; ++nj) wmma::fill_fragment(acc[mi][nj], 0.0f);

    #pragma unroll
    for (int kk = 0; kk < 64; kk += 16) {
        wmma::fragment<wmma::matrix_a, 16, 16, 16, __nv_bfloat16, wmma::row_major> af[2];
        wmma::load_matrix_sync(af[0], Qs + (wm * 32 +  0) * LDT + kk, LDT);
        wmma::load_matrix_sync(af[1], Qs + (wm * 32 + 16) * LDT + kk, LDT);
        #pragma unroll
        for (int nj = 0; nj < 4; ++nj) {
            wmma::fragment<wmma::matrix_b, 16, 16, 16, __nv_bfloat16, wmma::col_major> bf;
            wmma::load_matrix_sync(bf, Ks + (wc * 64 + nj * 16) * LDT + kk, LDT);
            wmma::mma_sync(acc[0][nj], af[0], bf, acc[0][nj]);
            wmma::mma_sync(acc[1][nj], af[1], bf, acc[1][nj]);
        }
    }

    #pragma unroll
    for (int mi = 0; mi < 2; ++mi) {
        float* Sp = S + ((size_t)b * NPIX + i0 + wm * 32 + mi * 16) * NPIX + j0 + wc * 64;
        #pragma unroll
        for (int nj = 0; nj < 4; ++nj)
            wmma::store_matrix_sync(Sp + nj * 16, acc[mi][nj], NPIX, wmma::mem_row_major);
    }
}

// ---------------- kernel 3: softmax row -> att = 1/(1+exp(p)), split bf16 ---
__global__ void att_kernel(const float* __restrict__ S,
                           __nv_bfloat16* __restrict__ AH,
                           __nv_bfloat16* __restrict__ AL) {
    const size_t roff = ((size_t)blockIdx.y * NPIX + blockIdx.x) * (size_t)NPIX;
    const float* r = S + roff;
    const int t = threadIdx.x;
    const int lane = t & 31, wid = t >> 5;
    __shared__ float smax[8];
    __shared__ float ssum[8];

    float v[16];
    float mx = -1e30f;
    #pragma unroll
    for (int q = 0; q < 16; ++q) { v[q] = r[t + q * 256]; mx = fmaxf(mx, v[q]); }
    #pragma unroll
    for (int o = 16; o; o >>= 1) mx = fmaxf(mx, __shfl_xor_sync(0xffffffffu, mx, o));
    if (lane == 0) smax[wid] = mx;
    __syncthreads();
    mx = smax[0];
    #pragma unroll
    for (int w = 1; w < 8; ++w) mx = fmaxf(mx, smax[w]);

    float s = 0.f;
    #pragma unroll
    for (int q = 0; q < 16; ++q) { v[q] = expf(v[q] - mx); s += v[q]; }
    #pragma unroll
    for (int o = 16; o; o >>= 1) s += __shfl_xor_sync(0xffffffffu, s, o);
    if (lane == 0) ssum[wid] = s;
    __syncthreads();
    float Z = 0.f;
    #pragma unroll
    for (int w = 0; w < 8; ++w) Z += ssum[w];
    float inv = 1.0f / Z;

    #pragma unroll
    for (int q = 0; q < 16; ++q) {
        float p = v[q] * inv;
        float a = 1.0f / (1.0f + expf(p));   // 1 - sigmoid(p)
        __nv_bfloat16 h = __float2bfloat16(a);
        AH[roff + t + q * 256] = h;
        AL[roff + t + q * 256] = __float2bfloat16(a - __bfloat162float(h));
    }
}

// ---------------- kernel 4: PV via wmma, 3-segment split precision ----------
// out[b,c,m] = alpha * sum_n att[m,n]*V[c,n] + x[b,c,m]
// CTA 128m x 256c, 8 warps (wm 0..3 x wc 0..1), warp tile 32m x 128c
// K = 3 x 4096 in 64-chunks, 3-stage cp.async pipeline
#define PV_STAGE_B ((128 * LDT + 256 * LDT) * 2)   // 55296 bytes per stage
__global__ __launch_bounds__(256) void pv_wmma_kernel(const __nv_bfloat16* __restrict__ AH,
                                                      const __nv_bfloat16* __restrict__ AL,
                                                      const __nv_bfloat16* __restrict__ VH,
                                                      const __nv_bfloat16* __restrict__ VL,
                                                      const float* __restrict__ xres,
                                                      const float* __restrict__ alpha,
                                                      float* __restrict__ out) {
    extern __shared__ char dyn[];
    const int tid = threadIdx.x, w = tid >> 5;
    const int b  = blockIdx.y;
    const int m0 = blockIdx.x * 128;

    // align base to 256B
    uint32_t dynb = smem_u32(dyn);
    uint32_t base = (dynb + 255u) & ~255u;
    char* sb = dyn + (base - dynb);
    const uint32_t sbase = base;

    const __nv_bfloat16* segA[3];
    const __nv_bfloat16* segB[3];
    {
        const size_t aoff = ((size_t)b * NPIX + m0) * (size_t)NPIX;
        const size_t voff = (size_t)b * CH * NPIX;
        segA[0] = AH + aoff; segB[0] = VH + voff;   // Ah*Vh
        segA[1] = AL + aoff; segB[1] = VH + voff;   // Al*Vh
        segA[2] = AH + aoff; segB[2] = VL + voff;   // Ah*Vl
    }

    auto issue_stage = [&](int t) {
        const int s = t % 3;
        const uint32_t dA = sbase + (uint32_t)s * PV_STAGE_B;
        const uint32_t dB = dA + 128 * LDT * 2;
        const __nv_bfloat16* pa = segA[t >> 6];
        const __nv_bfloat16* pb = segB[t >> 6];
        const int n0 = (t & 63) << 6;
        #pragma unroll
        for (int p = 0; p < 4; ++p) {           // A: 128 rows x 64 bf16
            int idx = tid + p * 256;
            int row = idx >> 3, c8 = idx & 7;
            cpa16(dA + (uint32_t)(row * LDT + c8 * 8) * 2,
                  pa + (size_t)row * NPIX + n0 + c8 * 8);
        }
        #pragma unroll
        for (int p = 0; p < 8; ++p) {           // B: 256 rows x 64 bf16
            int idx = tid + p * 256;
            int row = idx >> 3, c8 = idx & 7;
            cpa16(dB + (uint32_t)(row * LDT + c8 * 8) * 2,
                  pb + (size_t)row * NPIX + n0 + c8 * 8);
        }
        cpa_commit();
    };

    const int wm = w >> 1, wc = w & 1;
    wmma::fragment<wmma::accumulator, 16, 16, 16, float> acc[2][8];
    #pragma unroll
    for (int mi = 0; mi < 2; ++mi)
        #pragma unroll
        for (int nj = 0; nj < 8; ++nj) wmma::fill_fragment(acc[mi][nj], 0.0f);

    issue_stage(0);
    issue_stage(1);

    for (int t = 0; t < 192; ++t) {
        if (t < 191) cpa_wait<1>(); else cpa_wait<0>();
        __syncthreads();

        const __nv_bfloat16* cA = (const __nv_bfloat16*)(sb + (size_t)(t % 3) * PV_STAGE_B);
        const __nv_bfloat16* cB = cA + 128 * LDT;
        #pragma unroll
        for (int kk = 0; kk < 64; kk += 16) {
            wmma::fragment<wmma::matrix_a, 16, 16, 16, __nv_bfloat16, wmma::row_major> af[2];
            wmma::load_matrix_sync(af[0], cA + (wm * 32 +  0) * LDT + kk, LDT);
            wmma::load_matrix_sync(af[1], cA + (wm * 32 + 16) * LDT + kk, LDT);
            #pragma unroll
            for (int nj = 0; nj < 8; ++nj) {
                wmma::fragment<wmma::matrix_b, 16, 16, 16, __nv_bfloat16, wmma::col_major> bf;
                wmma::load_matrix_sync(bf, cB + (wc * 128 + nj * 16) * LDT + kk, LDT);
                wmma::mma_sync(acc[0][nj], af[0], bf, acc[0][nj]);
                wmma::mma_sync(acc[1][nj], af[1], bf, acc[1][nj]);
            }
        }

        if (t + 2 < 192) issue_stage(t + 2);
    }

    // epilogue: out[b,c,m] = alpha*acc + x  (col-major fragment IO, coalesced in m)
    const float al = alpha[0];
    #pragma unroll
    for (int mi = 0; mi < 2; ++mi) {
        const int mg = m0 + wm * 32 + mi * 16;
        #pragma unroll
        for (int nj = 0; nj < 8; ++nj) {
            const int cg = wc * 128 + nj * 16;
            const size_t off = ((size_t)b * CH + cg) * NPIX + mg;
            wmma::fragment<wmma::accumulator, 16, 16, 16, float> xf;
            wmma::load_matrix_sync(xf, xres + off, NPIX, wmma::mem_col_major);
            #pragma unroll
            for (int e = 0; e < xf.num_elements; ++e)
                xf.x[e] = al * acc[mi][nj].x[e] + xf.x[e];
            wmma::store_matrix_sync(out + off, xf, NPIX, wmma::mem_col_major);
        }
    }
}

// ---------------- launch ----------------
extern "C" void kernel_launch(void* const* d_in, const int* in_sizes, int n_in,
                              void* d_out, int out_size) {
    const float* x1    = (const float*)d_in[0];
    const float* x2    = (const float*)d_in[1];
    const float* x     = (const float*)d_in[2];
    const float* gamma = (const float*)d_in[3];
    const float* beta  = (const float*)d_in[4];
    const float* mean  = (const float*)d_in[5];
    const float* var   = (const float*)d_in[6];
    const float* Wb    = (const float*)d_in[7];
    const float* bb    = (const float*)d_in[8];
    const float* Wc    = (const float*)d_in[9];
    const float* bc    = (const float*)d_in[10];
    const float* Wd    = (const float*)d_in[11];
    const float* bd    = (const float*)d_in[12];
    const float* alpha = (const float*)d_in[13];
    float* out = (float*)d_out;

    __nv_bfloat16 *Qp, *Kp, *VHp, *VLp, *AHp, *ALp;
    float* Sp;
    cudaGetSymbolAddress((void**)&Qp,  g_Qb);
    cudaGetSymbolAddress((void**)&Kp,  g_Kb);
    cudaGetSymbolAddress((void**)&VHp, g_VH);
    cudaGetSymbolAddress((void**)&VLp, g_VL);
    cudaGetSymbolAddress((void**)&Sp,  g_S);
    cudaGetSymbolAddress((void**)&AHp, g_AH);
    cudaGetSymbolAddress((void**)&ALp, g_AL);

    const int pv_smem = 3 * PV_STAGE_B + 256;   // 166,144 B
    cudaFuncSetAttribute(pv_wmma_kernel, cudaFuncAttributeMaxDynamicSharedMemorySize, pv_smem);

    prep_kernel<<<1, 256>>>(gamma, beta, mean, var);

    projqk_kernel<<<dim3(NPIX / 64, 1, BATCH), 256>>>(x1, Wb, bb, Qp);
    projqk_kernel<<<dim3(NPIX / 64, 1, BATCH), 256>>>(x2, Wc, bc, Kp);
    projv_kernel <<<dim3(NPIX / 64, CH / 64, BATCH), 256>>>(x, Wd, bd, VHp, VLp);

    qk_wmma_kernel<<<dim3(NPIX / 128, NPIX / 128, BATCH), 256>>>(Qp, Kp, Sp);

    att_kernel<<<dim3(NPIX, BATCH), 256>>>(Sp, AHp, ALp);

    pv_wmma_kernel<<<dim3(NPIX / 128, BATCH), 256, pv_smem>>>(AHp, ALp, VHp, VLp, x, alpha, out);
}

// round 4
// speedup vs baseline: 3.2990x; 1.4113x over previous
#include <cuda_runtime.h>
#include <cuda_bf16.h>
#include <mma.h>
#include <math.h>
#include <stdint.h>

using namespace nvcuda;

#define BATCH 4
#define CH    256
#define CKDIM 64
#define NPIX  4096
#define EPS   1e-5f
#define LDT   72            // smem tile leading dim (bf16 elements)

#define DINL __device__ __forceinline__

// ---------------- device scratch (static, allocation-free) ----------------
__device__ __align__(16) float g_scale[CH];
__device__ __align__(16) float g_shift[CH];
__device__ __align__(16) float g_sx  [BATCH * CH];                        // colsum of x
__device__ __align__(16) float g_base[BATCH * CH];                        // alpha*0.5*SumV
__device__ __align__(16) float g_XP [(size_t)BATCH * CH * NPIX];          // x + base
__device__ __align__(16) __nv_bfloat16 g_Qb[BATCH * NPIX * CKDIM];        // [b][i][64]
__device__ __align__(16) __nv_bfloat16 g_Kb[BATCH * NPIX * CKDIM];        // [b][j][64]
__device__ __align__(16) __nv_bfloat16 g_VH[(size_t)BATCH * CH * NPIX];   // [b][c][n]
__device__ __align__(16) float         g_S [(size_t)BATCH * NPIX * NPIX]; // fp32 scores
__device__ __align__(16) __nv_bfloat16 g_Aq[(size_t)BATCH * NPIX * NPIX]; // q = sig(p)-0.5

// ---------------- portable async-copy helpers (sm_80+ PTX) -----------------
DINL uint32_t smem_u32(const void* p) {
    uint32_t a;
    asm("{ .reg .u64 t; cvta.to.shared.u64 t, %1; cvt.u32.u64 %0, t; }"
        : "=r"(a) : "l"(p));
    return a;
}
DINL void cpa16(uint32_t dst, const void* src) {
    asm volatile("cp.async.cg.shared.global [%0], [%1], 16;"
                 :: "r"(dst), "l"(src) : "memory");
}
DINL void cpa_commit() { asm volatile("cp.async.commit_group;" ::: "memory"); }
template<int N> DINL void cpa_wait() {
    asm volatile("cp.async.wait_group %0;" :: "n"(N) : "memory");
}

// ---------------- kernel 0: fold BN ----------------
__global__ void prep_kernel(const float* __restrict__ gamma,
                            const float* __restrict__ beta,
                            const float* __restrict__ mean,
                            const float* __restrict__ var) {
    int c = threadIdx.x;
    if (c < CH) {
        float s = gamma[c] * rsqrtf(var[c] + EPS);
        g_scale[c] = s;
        g_shift[c] = beta[c] - mean[c] * s;
    }
}

// ---------------- kernel 0b: column sums of x -> sx[b][c] -------------------
__global__ void colsum_kernel(const float* __restrict__ x) {
    const int c = blockIdx.x, b = blockIdx.y;
    const float* row = x + ((size_t)b * CH + c) * NPIX;
    const int t = threadIdx.x;
    float s = 0.f;
    #pragma unroll
    for (int q = 0; q < 16; ++q) s += row[t + q * 256];
    #pragma unroll
    for (int o = 16; o; o >>= 1) s += __shfl_xor_sync(0xffffffffu, s, o);
    __shared__ float ws[8];
    if ((t & 31) == 0) ws[t >> 5] = s;
    __syncthreads();
    if (t == 0) {
        float tot = 0.f;
        #pragma unroll
        for (int w = 0; w < 8; ++w) tot += ws[w];
        g_sx[b * CH + c] = tot;
    }
}

// ---------------- kernel 0c: base[b][c] = alpha*0.5*(Wd[c,:]·sx[b,:] + N*bd) -
__global__ void sumv_kernel(const float* __restrict__ Wd,
                            const float* __restrict__ bd,
                            const float* __restrict__ alpha) {
    const int b = blockIdx.x;
    const int c = threadIdx.x;    // 256 threads
    __shared__ float sxs[CH];
    sxs[c] = g_sx[b * CH + c];
    __syncthreads();
    float dot = 0.f;
    const float* wr = Wd + (size_t)c * CH;
    #pragma unroll 8
    for (int k = 0; k < CH; ++k) dot += wr[k] * sxs[k];
    g_base[b * CH + c] = alpha[0] * 0.5f * (dot + (float)NPIX * bd[c]);
}

// ---------------- kernel 0d: x' = x + base[b][c] ----------------------------
__global__ void basex_kernel(const float* __restrict__ x) {
    size_t i = (size_t)blockIdx.x * blockDim.x + threadIdx.x;
    g_XP[i] = x[i] + g_base[i >> 12];
}

// ---------------- kernel 1a: Q/K projection (BN folded), bf16 out [b][n][64]
__global__ void projqk_kernel(const float* __restrict__ x,
                              const float* __restrict__ W,
                              const float* __restrict__ bias,
                              __nv_bfloat16* __restrict__ out) {
    __shared__ float As[16][65];
    __shared__ float Bs[16][65];
    const int b  = blockIdx.z;
    const int n0 = blockIdx.x * 64;
    const float* xb = x + (size_t)b * CH * NPIX;
    const int tid = threadIdx.x;
    const int tk = tid & 15;
    const int tn = tid >> 4;

    float acc[4][4] = {};
    for (int c0 = 0; c0 < CH; c0 += 16) {
        {
            int nn = tid & 63, cb = tid >> 6;
            #pragma unroll
            for (int r = 0; r < 4; ++r) {
                int cc = cb + r * 4;
                float v = xb[(size_t)(c0 + cc) * NPIX + n0 + nn];
                As[cc][nn] = v * g_scale[c0 + cc] + g_shift[c0 + cc];
            }
        }
        {
            int cc = tid & 15, kb = tid >> 4;
            #pragma unroll
            for (int r = 0; r < 4; ++r) {
                int kk = kb + r * 16;
                Bs[cc][kk] = W[(size_t)kk * CH + c0 + cc];
            }
        }
        __syncthreads();
        #pragma unroll
        for (int cc = 0; cc < 16; ++cc) {
            float a[4], bv[4];
            #pragma unroll
            for (int i = 0; i < 4; ++i) a[i]  = As[cc][tn + i * 16];
            #pragma unroll
            for (int j = 0; j < 4; ++j) bv[j] = Bs[cc][tk + j * 16];
            #pragma unroll
            for (int i = 0; i < 4; ++i)
                #pragma unroll
                for (int j = 0; j < 4; ++j) acc[i][j] += a[i] * bv[j];
        }
        __syncthreads();
    }
    __nv_bfloat16* ob = out + (size_t)b * NPIX * CKDIM;
    #pragma unroll
    for (int i = 0; i < 4; ++i) {
        int n = n0 + tn + i * 16;
        #pragma unroll
        for (int j = 0; j < 4; ++j) {
            int k = tk + j * 16;
            ob[(size_t)n * CKDIM + k] = __float2bfloat16(acc[i][j] + bias[k]);
        }
    }
}

// ---------------- kernel 1b: V projection, bf16 [b][d][n] -------------------
__global__ void projv_kernel(const float* __restrict__ x,
                             const float* __restrict__ W,
                             const float* __restrict__ bias,
                             __nv_bfloat16* __restrict__ vh) {
    __shared__ float As[16][65];
    __shared__ float Bs[16][65];
    const int b  = blockIdx.z;
    const int n0 = blockIdx.x * 64;
    const int d0 = blockIdx.y * 64;
    const float* xb = x + (size_t)b * CH * NPIX;
    const int tid = threadIdx.x;
    const int tn = tid & 15;
    const int td = tid >> 4;

    float acc[4][4] = {};
    for (int c0 = 0; c0 < CH; c0 += 16) {
        {
            int nn = tid & 63, cb = tid >> 6;
            #pragma unroll
            for (int r = 0; r < 4; ++r) {
                int cc = cb + r * 4;
                As[cc][nn] = xb[(size_t)(c0 + cc) * NPIX + n0 + nn];
            }
        }
        {
            int cc = tid & 15, db = tid >> 4;
            #pragma unroll
            for (int r = 0; r < 4; ++r) {
                int dd = db + r * 16;
                Bs[cc][dd] = W[(size_t)(d0 + dd) * CH + c0 + cc];
            }
        }
        __syncthreads();
        #pragma unroll
        for (int cc = 0; cc < 16; ++cc) {
            float a[4], w[4];
            #pragma unroll
            for (int j = 0; j < 4; ++j) a[j] = As[cc][tn + j * 16];
            #pragma unroll
            for (int i = 0; i < 4; ++i) w[i] = Bs[cc][td + i * 16];
            #pragma unroll
            for (int i = 0; i < 4; ++i)
                #pragma unroll
                for (int j = 0; j < 4; ++j) acc[i][j] += w[i] * a[j];
        }
        __syncthreads();
    }
    #pragma unroll
    for (int i = 0; i < 4; ++i) {
        int d = d0 + td + i * 16;
        float bd_ = bias[d];
        #pragma unroll
        for (int j = 0; j < 4; ++j) {
            int n = n0 + tn + j * 16;
            vh[((size_t)b * CH + d) * NPIX + n] = __float2bfloat16(acc[i][j] + bd_);
        }
    }
}

// ---------------- kernel 2: scores = Q @ K^T via wmma bf16 ------------------
__global__ __launch_bounds__(256) void qk_wmma_kernel(const __nv_bfloat16* __restrict__ Qb,
                                                      const __nv_bfloat16* __restrict__ Kb,
                                                      float* __restrict__ S) {
    __shared__ __align__(32) __nv_bfloat16 Qs[128 * LDT];
    __shared__ __align__(32) __nv_bfloat16 Ks[128 * LDT];
    const int tid = threadIdx.x, w = tid >> 5;
    const int b  = blockIdx.z;
    const int i0 = blockIdx.y * 128;
    const int j0 = blockIdx.x * 128;

    const uint4* gQ = (const uint4*)(Qb + ((size_t)b * NPIX + i0) * CKDIM);
    const uint4* gK = (const uint4*)(Kb + ((size_t)b * NPIX + j0) * CKDIM);
    #pragma unroll
    for (int p = 0; p < 4; ++p) {
        int idx = tid + p * 256;
        int row = idx >> 3, c8 = idx & 7;
        *(uint4*)&Qs[row * LDT + c8 * 8] = gQ[idx];
        *(uint4*)&Ks[row * LDT + c8 * 8] = gK[idx];
    }
    __syncthreads();

    const int wm = w >> 1, wc = w & 1;
    wmma::fragment<wmma::accumulator, 16, 16, 16, float> acc[2][4];
    #pragma unroll
    for (int mi = 0; mi < 2; ++mi)
        #pragma unroll
        for (int nj = 0; nj < 4; ++nj) wmma::fill_fragment(acc[mi][nj], 0.0f);

    #pragma unroll
    for (int kk = 0; kk < 64; kk += 16) {
        wmma::fragment<wmma::matrix_a, 16, 16, 16, __nv_bfloat16, wmma::row_major> af[2];
        wmma::load_matrix_sync(af[0], Qs + (wm * 32 +  0) * LDT + kk, LDT);
        wmma::load_matrix_sync(af[1], Qs + (wm * 32 + 16) * LDT + kk, LDT);
        #pragma unroll
        for (int nj = 0; nj < 4; ++nj) {
            wmma::fragment<wmma::matrix_b, 16, 16, 16, __nv_bfloat16, wmma::col_major> bf;
            wmma::load_matrix_sync(bf, Ks + (wc * 64 + nj * 16) * LDT + kk, LDT);
            wmma::mma_sync(acc[0][nj], af[0], bf, acc[0][nj]);
            wmma::mma_sync(acc[1][nj], af[1], bf, acc[1][nj]);
        }
    }

    #pragma unroll
    for (int mi = 0; mi < 2; ++mi) {
        float* Sp = S + ((size_t)b * NPIX + i0 + wm * 32 + mi * 16) * NPIX + j0 + wc * 64;
        #pragma unroll
        for (int nj = 0; nj < 4; ++nj)
            wmma::store_matrix_sync(Sp + nj * 16, acc[mi][nj], NPIX, wmma::mem_row_major);
    }
}

// ---------------- kernel 3: softmax row -> q = 0.5*tanh(p/2) bf16 -----------
__global__ void att_kernel(const float* __restrict__ S,
                           __nv_bfloat16* __restrict__ Aq) {
    const size_t roff = ((size_t)blockIdx.y * NPIX + blockIdx.x) * (size_t)NPIX;
    const float* r = S + roff;
    const int t = threadIdx.x;
    const int lane = t & 31, wid = t >> 5;
    __shared__ float smax[8];
    __shared__ float ssum[8];

    float v[16];
    float mx = -1e30f;
    #pragma unroll
    for (int q = 0; q < 16; ++q) { v[q] = r[t + q * 256]; mx = fmaxf(mx, v[q]); }
    #pragma unroll
    for (int o = 16; o; o >>= 1) mx = fmaxf(mx, __shfl_xor_sync(0xffffffffu, mx, o));
    if (lane == 0) smax[wid] = mx;
    __syncthreads();
    mx = smax[0];
    #pragma unroll
    for (int w = 1; w < 8; ++w) mx = fmaxf(mx, smax[w]);

    float s = 0.f;
    #pragma unroll
    for (int q = 0; q < 16; ++q) { v[q] = expf(v[q] - mx); s += v[q]; }
    #pragma unroll
    for (int o = 16; o; o >>= 1) s += __shfl_xor_sync(0xffffffffu, s, o);
    if (lane == 0) ssum[wid] = s;
    __syncthreads();
    float Z = 0.f;
    #pragma unroll
    for (int w = 0; w < 8; ++w) Z += ssum[w];
    float inv = 1.0f / Z;

    #pragma unroll
    for (int q = 0; q < 16; ++q) {
        float p = v[q] * inv;                     // softmax value
        float qq = 0.5f * tanhf(0.5f * p);        // sigmoid(p) - 0.5
        Aq[roff + t + q * 256] = __float2bfloat16(qq);
    }
}

// ---------------- kernel 4: out[b,c,m] = x'[b,c,m] - alpha * sum_n q*V ------
// single bf16 GEMM: CTA 128m x 256c, 8 warps, K=4096 in 64-chunks, 3 stages
#define PV_STAGE_B ((128 * LDT + 256 * LDT) * 2)   // 55296 bytes per stage
__global__ __launch_bounds__(256) void pv_wmma_kernel(const __nv_bfloat16* __restrict__ Aq,
                                                      const __nv_bfloat16* __restrict__ VH,
                                                      const float* __restrict__ alpha,
                                                      float* __restrict__ out) {
    extern __shared__ char dyn[];
    const int tid = threadIdx.x, w = tid >> 5;
    const int b  = blockIdx.y;
    const int m0 = blockIdx.x * 128;

    uint32_t dynb = smem_u32(dyn);
    uint32_t base = (dynb + 255u) & ~255u;
    char* sb = dyn + (base - dynb);
    const uint32_t sbase = base;

    const __nv_bfloat16* pa = Aq + ((size_t)b * NPIX + m0) * (size_t)NPIX;
    const __nv_bfloat16* pb = VH + (size_t)b * CH * NPIX;

    auto issue_stage = [&](int t) {
        const int s = t % 3;
        const uint32_t dA = sbase + (uint32_t)s * PV_STAGE_B;
        const uint32_t dB = dA + 128 * LDT * 2;
        const int n0 = t << 6;
        #pragma unroll
        for (int p = 0; p < 4; ++p) {           // A: 128 rows x 64 bf16
            int idx = tid + p * 256;
            int row = idx >> 3, c8 = idx & 7;
            cpa16(dA + (uint32_t)(row * LDT + c8 * 8) * 2,
                  pa + (size_t)row * NPIX + n0 + c8 * 8);
        }
        #pragma unroll
        for (int p = 0; p < 8; ++p) {           // B: 256 rows x 64 bf16
            int idx = tid + p * 256;
            int row = idx >> 3, c8 = idx & 7;
            cpa16(dB + (uint32_t)(row * LDT + c8 * 8) * 2,
                  pb + (size_t)row * NPIX + n0 + c8 * 8);
        }
        cpa_commit();
    };

    const int wm = w >> 1, wc = w & 1;
    wmma::fragment<wmma::accumulator, 16, 16, 16, float> acc[2][8];
    #pragma unroll
    for (int mi = 0; mi < 2; ++mi)
        #pragma unroll
        for (int nj = 0; nj < 8; ++nj) wmma::fill_fragment(acc[mi][nj], 0.0f);

    issue_stage(0);
    issue_stage(1);

    for (int t = 0; t < 64; ++t) {
        if (t < 63) cpa_wait<1>(); else cpa_wait<0>();
        __syncthreads();

        const __nv_bfloat16* cA = (const __nv_bfloat16*)(sb + (size_t)(t % 3) * PV_STAGE_B);
        const __nv_bfloat16* cB = cA + 128 * LDT;
        #pragma unroll
        for (int kk = 0; kk < 64; kk += 16) {
            wmma::fragment<wmma::matrix_a, 16, 16, 16, __nv_bfloat16, wmma::row_major> af[2];
            wmma::load_matrix_sync(af[0], cA + (wm * 32 +  0) * LDT + kk, LDT);
            wmma::load_matrix_sync(af[1], cA + (wm * 32 + 16) * LDT + kk, LDT);
            #pragma unroll
            for (int nj = 0; nj < 8; ++nj) {
                wmma::fragment<wmma::matrix_b, 16, 16, 16, __nv_bfloat16, wmma::col_major> bf;
                wmma::load_matrix_sync(bf, cB + (wc * 128 + nj * 16) * LDT + kk, LDT);
                wmma::mma_sync(acc[0][nj], af[0], bf, acc[0][nj]);
                wmma::mma_sync(acc[1][nj], af[1], bf, acc[1][nj]);
            }
        }

        if (t + 2 < 64) issue_stage(t + 2);
    }

    // epilogue: out = x' - alpha*acc  (col-major fragment IO, coalesced in m)
    const float al = alpha[0];
    #pragma unroll
    for (int mi = 0; mi < 2; ++mi) {
        const int mg = m0 + wm * 32 + mi * 16;
        #pragma unroll
        for (int nj = 0; nj < 8; ++nj) {
            const int cg = wc * 128 + nj * 16;
            const size_t off = ((size_t)b * CH + cg) * NPIX + mg;
            wmma::fragment<wmma::accumulator, 16, 16, 16, float> xf;
            wmma::load_matrix_sync(xf, g_XP + off, NPIX, wmma::mem_col_major);
            #pragma unroll
            for (int e = 0; e < xf.num_elements; ++e)
                xf.x[e] = xf.x[e] - al * acc[mi][nj].x[e];
            wmma::store_matrix_sync(out + off, xf, NPIX, wmma::mem_col_major);
        }
    }
}

// ---------------- launch ----------------
extern "C" void kernel_launch(void* const* d_in, const int* in_sizes, int n_in,
                              void* d_out, int out_size) {
    const float* x1    = (const float*)d_in[0];
    const float* x2    = (const float*)d_in[1];
    const float* x     = (const float*)d_in[2];
    const float* gamma = (const float*)d_in[3];
    const float* beta  = (const float*)d_in[4];
    const float* mean  = (const float*)d_in[5];
    const float* var   = (const float*)d_in[6];
    const float* Wb    = (const float*)d_in[7];
    const float* bb    = (const float*)d_in[8];
    const float* Wc    = (const float*)d_in[9];
    const float* bc    = (const float*)d_in[10];
    const float* Wd    = (const float*)d_in[11];
    const float* bd    = (const float*)d_in[12];
    const float* alpha = (const float*)d_in[13];
    float* out = (float*)d_out;

    __nv_bfloat16 *Qp, *Kp, *VHp, *Aqp;
    float* Sp;
    cudaGetSymbolAddress((void**)&Qp,  g_Qb);
    cudaGetSymbolAddress((void**)&Kp,  g_Kb);
    cudaGetSymbolAddress((void**)&VHp, g_VH);
    cudaGetSymbolAddress((void**)&Sp,  g_S);
    cudaGetSymbolAddress((void**)&Aqp, g_Aq);

    const int pv_smem = 3 * PV_STAGE_B + 256;   // 166,144 B
    cudaFuncSetAttribute(pv_wmma_kernel, cudaFuncAttributeMaxDynamicSharedMemorySize, pv_smem);

    prep_kernel<<<1, 256>>>(gamma, beta, mean, var);
    colsum_kernel<<<dim3(CH, BATCH), 256>>>(x);
    sumv_kernel<<<BATCH, CH>>>(Wd, bd, alpha);
    basex_kernel<<<(BATCH * CH * NPIX) / 1024, 1024>>>(x);

    projqk_kernel<<<dim3(NPIX / 64, 1, BATCH), 256>>>(x1, Wb, bb, Qp);
    projqk_kernel<<<dim3(NPIX / 64, 1, BATCH), 256>>>(x2, Wc, bc, Kp);
    projv_kernel <<<dim3(NPIX / 64, CH / 64, BATCH), 256>>>(x, Wd, bd, VHp);

    qk_wmma_kernel<<<dim3(NPIX / 128, NPIX / 128, BATCH), 256>>>(Qp, Kp, Sp);

    att_kernel<<<dim3(NPIX, BATCH), 256>>>(Sp, Aqp);

    pv_wmma_kernel<<<dim3(NPIX / 128, BATCH), 256, pv_smem>>>(Aqp, VHp, alpha, out);
}